// round 12
// baseline (speedup 1.0000x reference)
#include <cuda_runtime.h>
#include <math.h>
#include <stdint.h>

#define N_ROWS   8192
#define N_PROP   2000
#define THREADS  256
#define NWARPS   (THREADS / 32)
#define ROWSBLK  2
#define GRID     (N_ROWS / ROWSBLK)   // 4096
#define CHUNK    256
#define NCHUNKS  8                    // per row: 7*256 + 208
#define TAILN    208
#define TOTCH    (ROWSBLK * NCHUNKS)  // 16
#define NBUF     3
#define RPN_CB   (CHUNK * 5 * 4)      // 5120 B
#define SC_CB    (CHUNK * 2 * 4)      // 2048 B
#define RPN_TB   (TAILN * 5 * 4)      // 4160 B
#define SC_TB    (TAILN * 2 * 4)      // 1664 B
#define BUF_STRIDE (RPN_CB + SC_CB)   // 7168, 128B-aligned

// d_in[0]=rois (N,4), d_in[1]=rpn_rois (N,NP,5), d_in[2]=scores (N,NP,2)
// d_out = [sel_rpn_rois (N,4) | sel_scores (N,1)]

struct RefStats { float x, y, s, inv_s, r_max, piw, wsq; };

__device__ __forceinline__ uint32_t smem_u32(const void* p) {
    uint32_t a;
    asm("{ .reg .u64 t; cvta.to.shared.u64 t, %1; cvt.u32.u64 %0, t; }"
        : "=r"(a) : "l"(p));
    return a;
}
__device__ __forceinline__ float rcp_approx(float a) {
    float r; asm("rcp.approx.ftz.f32 %0, %1;" : "=f"(r) : "f"(a)); return r;
}
__device__ __forceinline__ float ex2_approx(float a) {
    float r; asm("ex2.approx.ftz.f32 %0, %1;" : "=f"(r) : "f"(a)); return r;
}
__device__ __forceinline__ void mbar_init(uint32_t mbar, uint32_t cnt) {
    asm volatile("mbarrier.init.shared.b64 [%0], %1;" :: "r"(mbar), "r"(cnt) : "memory");
}
__device__ __forceinline__ void mbar_arrive(uint32_t mbar) {
    asm volatile("mbarrier.arrive.shared.b64 _, [%0];" :: "r"(mbar) : "memory");
}
__device__ __forceinline__ void mbar_expect_tx(uint32_t mbar, uint32_t bytes) {
    asm volatile("mbarrier.arrive.expect_tx.shared.b64 _, [%0], %1;"
                 :: "r"(mbar), "r"(bytes) : "memory");
}
__device__ __forceinline__ void bulk_g2s(uint32_t dst, const void* src,
                                         uint32_t bytes, uint32_t mbar) {
    asm volatile("cp.async.bulk.shared::cta.global.mbarrier::complete_tx::bytes "
                 "[%0], [%1], %2, [%3];"
                 :: "r"(dst), "l"(src), "r"(bytes), "r"(mbar) : "memory");
}
__device__ __forceinline__ void mbar_wait(uint32_t mbar, uint32_t parity) {
    asm volatile(
        "{\n\t"
        ".reg .pred P;\n\t"
        "WL_%=:\n\t"
        "mbarrier.try_wait.parity.acquire.cta.shared::cta.b64 P, [%0], %1, 0x989680;\n\t"
        "@P bra.uni WD_%=;\n\t"
        "bra.uni WL_%=;\n\t"
        "WD_%=:\n\t"
        "}" :: "r"(mbar), "r"(parity) : "memory");
}
__device__ __forceinline__ void mbar_wait_relaxed(uint32_t mbar, uint32_t parity) {
    asm volatile(
        "{\n\t"
        ".reg .pred P;\n\t"
        "WL_%=:\n\t"
        "mbarrier.try_wait.parity.relaxed.cta.shared::cta.b64 P, [%0], %1, 0x989680;\n\t"
        "@P bra.uni WD_%=;\n\t"
        "bra.uni WL_%=;\n\t"
        "WD_%=:\n\t"
        "}" :: "r"(mbar), "r"(parity) : "memory");
}

// exp(y) for y <= 0, ~2ulp
__device__ __forceinline__ float fast_exp_neg(float y) {
    float z  = fmaxf(y * 1.4426950408889634f, -127.0f);
    float fn = rintf(z);
    float m  = ex2_approx(z - fn);
    float sc = __int_as_float(((int)fn + 127) << 23);
    return m * sc;
}

// hanning(t) = cos^2(t/2), Taylor on t/2 in [0, 1.6], err < 1e-8
__device__ __forceinline__ float hann_from_t(float t) {
    float th = t * 0.5f;
    float u  = th * th;
    float P = 2.0876757e-9f;
    P = fmaf(P, u, -2.7557319e-7f);
    P = fmaf(P, u,  2.4801587e-5f);
    P = fmaf(P, u, -1.3888889e-3f);
    P = fmaf(P, u,  4.1666667e-2f);
    P = fmaf(P, u, -0.5f);
    P = fmaf(P, u,  1.0f);
    return P * P;
}

__device__ __forceinline__ float prop_score(const RefStats& R,
                                            float a0, float a1, float a2, float a3,
                                            float sc)
{
    const float x_ = (a0 + a2) * 0.5f;
    const float y_ = (a1 + a3) * 0.5f;
    const float w_ = fabsf(a0 - a2) + 1e-4f;
    const float h_ = fabsf(a1 - a3) + 1e-4f;
    const float p_ = (w_ + h_) * 0.5f;
    const float q  = (w_ + p_) * (h_ + p_);
    const float s_ = q * rsqrtf(q);

    const float smax = fmaxf(R.s * rcp_approx(s_), s_ * R.inv_s);
    const float pen  = fast_exp_neg(fmaf(smax * R.r_max, -0.055f, 0.055f));

    const float dx  = R.x - x_;
    const float dy  = R.y - y_;
    const float d2  = fmaf(dx, dx, dy * dy);
    const float d2g = fmaxf(d2, 1e-36f);
    const float dist = d2g * rsqrtf(d2g);
    const float t   = fminf(dist * R.piw, 3.2f);
    float han = hann_from_t(t);
    han = (d2 > R.wsq) ? 0.0f : han;

    return fmaf(sc, pen, 0.42f * han);
}

// Issue global chunk cg in the 2-row ring: row = row0 + cg/8, c = cg%8
__device__ __forceinline__ void issue_chunk(int cg, int row0, uint32_t mbf, uint32_t bb,
                                            const char* rpnb, const char* scb)
{
    const int row = row0 + (cg >> 3);
    const int c   = cg & (NCHUNKS - 1);
    const int b   = cg % NBUF;
    const uint32_t m = mbf + 8u * b;
    const uint32_t d = bb + b * BUF_STRIDE;
    const uint32_t rbytes = (c == NCHUNKS - 1) ? RPN_TB : RPN_CB;
    const uint32_t sbytes = (c == NCHUNKS - 1) ? SC_TB  : SC_CB;
    const char* rrow = rpnb + (size_t)row * (N_PROP * 5 * 4);
    const char* srow = scb  + (size_t)row * (N_PROP * 2 * 4);
    mbar_expect_tx(m, rbytes + sbytes);
    bulk_g2s(d,          rrow + (size_t)c * RPN_CB, rbytes, m);
    bulk_g2s(d + RPN_CB, srow + (size_t)c * SC_CB,  sbytes, m);
}

__global__ __launch_bounds__(THREADS)
void trnms_kernel(const float* __restrict__ rois,
                  const float* __restrict__ rpn,
                  const float* __restrict__ scores,
                  float* __restrict__ out)
{
    const int row0 = blockIdx.x * ROWSBLK;
    const int tid  = threadIdx.x;
    const int lane = tid & 31;
    const int wid  = tid >> 5;

    __shared__ __align__(128) unsigned char sbuf[NBUF * BUF_STRIDE];  // 21504 B
    __shared__ __align__(8)  uint64_t mbar_full[NBUF];
    __shared__ __align__(8)  uint64_t mbar_empty[NBUF];
    __shared__ float sv[NWARPS];
    __shared__ int   si[NWARPS];

    const uint32_t mbf = smem_u32(mbar_full);
    const uint32_t mbe = smem_u32(mbar_empty);
    const uint32_t bb  = smem_u32(sbuf);

    // Start the copies FIRST — nothing depends on rois yet.
    if (tid == 0) {
        #pragma unroll
        for (int b = 0; b < NBUF; b++) {
            mbar_init(mbf + 8u * b, 1);
            mbar_init(mbe + 8u * b, NWARPS);
        }
        asm volatile("fence.proxy.async.shared::cta;" ::: "memory");
    }
    __syncthreads();
    if (tid == 0) {
        #pragma unroll
        for (int cg = 0; cg < NBUF; cg++)
            issue_chunk(cg, row0, mbf, bb, (const char*)rpn, (const char*)scores);
    }

    RefStats R;
    float best = -INFINITY;
    int   bidx = 0x7fffffff;
    int   row  = row0;

    #pragma unroll
    for (int cg = 0; cg < TOTCH; cg++) {
        const int c = cg & (NCHUNKS - 1);
        if (c == 0) {
            row = row0 + (cg >> 3);
            const float4 rr = *reinterpret_cast<const float4*>(rois + (size_t)row * 4);
            R.x = (rr.x + rr.z) * 0.5f;
            R.y = (rr.y + rr.w) * 0.5f;
            const float w = fabsf(rr.x - rr.z) + 1e-4f;
            const float h = fabsf(rr.y - rr.w) + 1e-4f;
            const float p = (w + h) * 0.5f;
            R.s = sqrtf((w + p) * (h + p));
            R.inv_s = __fdiv_rn(1.0f, R.s);
            const float ratio = __fdiv_rn(w, h);
            R.r_max = fmaxf(ratio, __fdiv_rn(1.0f, ratio));
            const float window = R.s * 2.0f;
            R.piw = __fdiv_rn(3.14159274101257324219f, window);
            R.wsq = window * window;
            best = -INFINITY;
            bidx = 0x7fffffff;
        }

        const int b   = cg % NBUF;
        const int phf = (cg / NBUF) & 1;
        mbar_wait(mbf + 8u * b, phf);            // consumer: data ready

        const int cnt = (c == NCHUNKS - 1) ? TAILN : CHUNK;
        if (tid < cnt) {
            const float* rchunk = reinterpret_cast<const float*>(sbuf + b * BUF_STRIDE);
            const float* schunk = reinterpret_cast<const float*>(sbuf + b * BUF_STRIDE + RPN_CB);

            const float a0 = rchunk[tid * 5 + 1];
            const float a1 = rchunk[tid * 5 + 2];
            const float a2 = rchunk[tid * 5 + 3];
            const float a3 = rchunk[tid * 5 + 4];
            const float2 s2 = *reinterpret_cast<const float2*>(schunk + tid * 2);

            const float pw = prop_score(R, a0, a1, a2, a3, s2.y);
            const int j = c * CHUNK + tid;       // ascending per thread within row
            if (pw > best) { best = pw; bidx = j; }
        }

        if (c == NCHUNKS - 1) {
            // ---- row finished: block argmax reduce + gather ----
            float rb = best; int ri = bidx;
            #pragma unroll
            for (int off = 16; off > 0; off >>= 1) {
                const float ov = __shfl_down_sync(0xffffffffu, rb, off);
                const int   oi = __shfl_down_sync(0xffffffffu, ri, off);
                if (ov > rb || (ov == rb && oi < ri)) { rb = ov; ri = oi; }
            }
            if (lane == 0) { sv[wid] = rb; si[wid] = ri; }
            __syncthreads();
            if (wid == 0) {
                rb = (lane < NWARPS) ? sv[lane] : -INFINITY;
                ri = (lane < NWARPS) ? si[lane] : 0x7fffffff;
                #pragma unroll
                for (int off = NWARPS / 2; off > 0; off >>= 1) {
                    const float ov = __shfl_down_sync(0xffffffffu, rb, off);
                    const int   oi = __shfl_down_sync(0xffffffffu, ri, off);
                    if (ov > rb || (ov == rb && oi < ri)) { rb = ov; ri = oi; }
                }
                if (lane == 0) {
                    const float* q = rpn + (size_t)row * (N_PROP * 5) + (long long)ri * 5;
                    float* o = out + (size_t)row * 4;
                    o[0] = q[1];
                    o[1] = q[2];
                    o[2] = q[3];
                    o[3] = q[4];
                    out[(size_t)N_ROWS * 4 + row] =
                        scores[(size_t)row * (N_PROP * 2) + ri * 2 + 1];
                }
            }
        }

        if (cg + NBUF < TOTCH) {                 // buffer b will be recycled
            __syncwarp();
            if (lane == 0) mbar_arrive(mbe + 8u * b);
            if (tid == 0) {
                mbar_wait_relaxed(mbe + 8u * b, (cg / NBUF) & 1);
                issue_chunk(cg + NBUF, row0, mbf, bb,
                            (const char*)rpn, (const char*)scores);
            }
        }
    }
}

extern "C" void kernel_launch(void* const* d_in, const int* in_sizes, int n_in,
                              void* d_out, int out_size)
{
    const float* rois   = (const float*)d_in[0];
    const float* rpn    = (const float*)d_in[1];
    const float* scores = (const float*)d_in[2];
    float* out = (float*)d_out;

    trnms_kernel<<<GRID, THREADS>>>(rois, rpn, scores, out);
}

// round 13
// speedup vs baseline: 1.0056x; 1.0056x over previous
#include <cuda_runtime.h>
#include <math.h>
#include <stdint.h>

#define N_ROWS   8192
#define N_PROP   2000
#define THREADS  128
#define NWARPS   (THREADS / 32)       // 4
#define CHUNK    128
#define NCHUNKS  16                   // 15*128 + 80 = 2000
#define TAILN    80
#define NBUF     3
#define RPN_CB   (CHUNK * 5 * 4)      // 2560 B (16B mult)
#define SC_CB    (CHUNK * 2 * 4)      // 1024 B
#define RPN_TB   (TAILN * 5 * 4)      // 1600 B (16B mult)
#define SC_TB    (TAILN * 2 * 4)      // 640 B (16B mult)
#define BUF_STRIDE (RPN_CB + SC_CB)   // 3584, 128B-aligned

// d_in[0]=rois (N,4), d_in[1]=rpn_rois (N,NP,5), d_in[2]=scores (N,NP,2)
// d_out = [sel_rpn_rois (N,4) | sel_scores (N,1)]

struct RefStats { float x, y, s, inv_s, r_max, piw, wsq; };

__device__ __forceinline__ uint32_t smem_u32(const void* p) {
    uint32_t a;
    asm("{ .reg .u64 t; cvta.to.shared.u64 t, %1; cvt.u32.u64 %0, t; }"
        : "=r"(a) : "l"(p));
    return a;
}
__device__ __forceinline__ float rcp_approx(float a) {
    float r; asm("rcp.approx.ftz.f32 %0, %1;" : "=f"(r) : "f"(a)); return r;
}
__device__ __forceinline__ float ex2_approx(float a) {
    float r; asm("ex2.approx.ftz.f32 %0, %1;" : "=f"(r) : "f"(a)); return r;
}
__device__ __forceinline__ void mbar_init(uint32_t mbar, uint32_t cnt) {
    asm volatile("mbarrier.init.shared.b64 [%0], %1;" :: "r"(mbar), "r"(cnt) : "memory");
}
__device__ __forceinline__ void mbar_arrive(uint32_t mbar) {
    asm volatile("mbarrier.arrive.shared.b64 _, [%0];" :: "r"(mbar) : "memory");
}
__device__ __forceinline__ void mbar_expect_tx(uint32_t mbar, uint32_t bytes) {
    asm volatile("mbarrier.arrive.expect_tx.shared.b64 _, [%0], %1;"
                 :: "r"(mbar), "r"(bytes) : "memory");
}
__device__ __forceinline__ void bulk_g2s(uint32_t dst, const void* src,
                                         uint32_t bytes, uint32_t mbar) {
    asm volatile("cp.async.bulk.shared::cta.global.mbarrier::complete_tx::bytes "
                 "[%0], [%1], %2, [%3];"
                 :: "r"(dst), "l"(src), "r"(bytes), "r"(mbar) : "memory");
}
__device__ __forceinline__ void mbar_wait(uint32_t mbar, uint32_t parity) {
    asm volatile(
        "{\n\t"
        ".reg .pred P;\n\t"
        "WL_%=:\n\t"
        "mbarrier.try_wait.parity.acquire.cta.shared::cta.b64 P, [%0], %1, 0x989680;\n\t"
        "@P bra.uni WD_%=;\n\t"
        "bra.uni WL_%=;\n\t"
        "WD_%=:\n\t"
        "}" :: "r"(mbar), "r"(parity) : "memory");
}
__device__ __forceinline__ void mbar_wait_relaxed(uint32_t mbar, uint32_t parity) {
    asm volatile(
        "{\n\t"
        ".reg .pred P;\n\t"
        "WL_%=:\n\t"
        "mbarrier.try_wait.parity.relaxed.cta.shared::cta.b64 P, [%0], %1, 0x989680;\n\t"
        "@P bra.uni WD_%=;\n\t"
        "bra.uni WL_%=;\n\t"
        "WD_%=:\n\t"
        "}" :: "r"(mbar), "r"(parity) : "memory");
}

// exp(y) for y <= 0, ~2ulp
__device__ __forceinline__ float fast_exp_neg(float y) {
    float z  = fmaxf(y * 1.4426950408889634f, -127.0f);
    float fn = rintf(z);
    float m  = ex2_approx(z - fn);
    float sc = __int_as_float(((int)fn + 127) << 23);
    return m * sc;
}

// hanning(t) = cos^2(t/2), Taylor on t/2 in [0, 1.6], err < 1e-8
__device__ __forceinline__ float hann_from_t(float t) {
    float th = t * 0.5f;
    float u  = th * th;
    float P = 2.0876757e-9f;
    P = fmaf(P, u, -2.7557319e-7f);
    P = fmaf(P, u,  2.4801587e-5f);
    P = fmaf(P, u, -1.3888889e-3f);
    P = fmaf(P, u,  4.1666667e-2f);
    P = fmaf(P, u, -0.5f);
    P = fmaf(P, u,  1.0f);
    return P * P;
}

__device__ __forceinline__ float prop_score(const RefStats& R,
                                            float a0, float a1, float a2, float a3,
                                            float sc)
{
    const float x_ = (a0 + a2) * 0.5f;
    const float y_ = (a1 + a3) * 0.5f;
    const float w_ = fabsf(a0 - a2) + 1e-4f;
    const float h_ = fabsf(a1 - a3) + 1e-4f;
    const float p_ = (w_ + h_) * 0.5f;
    const float q  = (w_ + p_) * (h_ + p_);
    const float s_ = q * rsqrtf(q);

    const float smax = fmaxf(R.s * rcp_approx(s_), s_ * R.inv_s);
    const float pen  = fast_exp_neg(fmaf(smax * R.r_max, -0.055f, 0.055f));

    const float dx  = R.x - x_;
    const float dy  = R.y - y_;
    const float d2  = fmaf(dx, dx, dy * dy);
    const float d2g = fmaxf(d2, 1e-36f);
    const float dist = d2g * rsqrtf(d2g);
    const float t   = fminf(dist * R.piw, 3.2f);
    float han = hann_from_t(t);
    han = (d2 > R.wsq) ? 0.0f : han;

    return fmaf(sc, pen, 0.42f * han);
}

__device__ __forceinline__ void issue_chunk(int c, uint32_t mbf, uint32_t bb,
                                            const char* rrow, const char* srow)
{
    const int b = c % NBUF;
    const uint32_t m = mbf + 8u * b;
    const uint32_t d = bb + b * BUF_STRIDE;
    const uint32_t rbytes = (c == NCHUNKS - 1) ? RPN_TB : RPN_CB;
    const uint32_t sbytes = (c == NCHUNKS - 1) ? SC_TB  : SC_CB;
    mbar_expect_tx(m, rbytes + sbytes);
    bulk_g2s(d,          rrow + (size_t)c * RPN_CB, rbytes, m);
    bulk_g2s(d + RPN_CB, srow + (size_t)c * SC_CB,  sbytes, m);
}

__global__ __launch_bounds__(THREADS, 16)
void trnms_kernel(const float* __restrict__ rois,
                  const float* __restrict__ rpn,
                  const float* __restrict__ scores,
                  float* __restrict__ out)
{
    const int row = blockIdx.x;
    const int tid = threadIdx.x;
    const int lane = tid & 31;
    const int wid  = tid >> 5;

    __shared__ __align__(128) unsigned char sbuf[NBUF * BUF_STRIDE];  // 10752 B
    __shared__ __align__(8)  uint64_t mbar_full[NBUF];
    __shared__ __align__(8)  uint64_t mbar_empty[NBUF];
    __shared__ float sv[NWARPS];
    __shared__ int   si[NWARPS];

    const uint32_t mbf = smem_u32(mbar_full);
    const uint32_t mbe = smem_u32(mbar_empty);
    const uint32_t bb  = smem_u32(sbuf);

    const char* rrow = (const char*)rpn    + (size_t)row * (N_PROP * 5 * 4);
    const char* srow = (const char*)scores + (size_t)row * (N_PROP * 2 * 4);

    // Copies first — nothing depends on rois yet.
    if (tid == 0) {
        #pragma unroll
        for (int b = 0; b < NBUF; b++) {
            mbar_init(mbf + 8u * b, 1);
            mbar_init(mbe + 8u * b, NWARPS);
        }
        asm volatile("fence.proxy.async.shared::cta;" ::: "memory");
    }
    __syncthreads();
    if (tid == 0) {
        #pragma unroll
        for (int c = 0; c < NBUF; c++) issue_chunk(c, mbf, bb, rrow, srow);
    }

    RefStats R;
    {
        const float4 rr = *reinterpret_cast<const float4*>(rois + (size_t)row * 4);
        R.x = (rr.x + rr.z) * 0.5f;
        R.y = (rr.y + rr.w) * 0.5f;
        const float w = fabsf(rr.x - rr.z) + 1e-4f;
        const float h = fabsf(rr.y - rr.w) + 1e-4f;
        const float p = (w + h) * 0.5f;
        R.s = sqrtf((w + p) * (h + p));
        R.inv_s = __fdiv_rn(1.0f, R.s);
        const float ratio = __fdiv_rn(w, h);
        R.r_max = fmaxf(ratio, __fdiv_rn(1.0f, ratio));
        const float window = R.s * 2.0f;
        R.piw = __fdiv_rn(3.14159274101257324219f, window);
        R.wsq = window * window;
    }

    float best = -INFINITY;
    int   bidx = 0x7fffffff;

    #pragma unroll
    for (int c = 0; c < NCHUNKS; c++) {
        const int b   = c % NBUF;
        const int phf = (c / NBUF) & 1;
        mbar_wait(mbf + 8u * b, phf);          // consumer: data ready

        const int cnt = (c == NCHUNKS - 1) ? TAILN : CHUNK;   // 128 for c<15
        if (tid < cnt) {
            const float* rchunk = reinterpret_cast<const float*>(sbuf + b * BUF_STRIDE);
            const float* schunk = reinterpret_cast<const float*>(sbuf + b * BUF_STRIDE + RPN_CB);

            const float a0 = rchunk[tid * 5 + 1];
            const float a1 = rchunk[tid * 5 + 2];
            const float a2 = rchunk[tid * 5 + 3];
            const float a3 = rchunk[tid * 5 + 4];
            const float2 s2 = *reinterpret_cast<const float2*>(schunk + tid * 2);

            const float pw = prop_score(R, a0, a1, a2, a3, s2.y);
            const int j = c * CHUNK + tid;     // ascending per thread
            if (pw > best) { best = pw; bidx = j; }
        }

        if (c + NBUF < NCHUNKS) {              // buffer will be recycled
            __syncwarp();
            if (lane == 0) mbar_arrive(mbe + 8u * b);   // this warp done with buffer b
            if (tid == 0) {
                mbar_wait_relaxed(mbe + 8u * b, (c / NBUF) & 1);
                issue_chunk(c + NBUF, mbf, bb, rrow, srow);
            }
        }
    }

    // ---- block argmax reduction, first-index wins on ties ----
    #pragma unroll
    for (int off = 16; off > 0; off >>= 1) {
        const float ov = __shfl_down_sync(0xffffffffu, best, off);
        const int   oi = __shfl_down_sync(0xffffffffu, bidx, off);
        if (ov > best || (ov == best && oi < bidx)) { best = ov; bidx = oi; }
    }
    if (lane == 0) { sv[wid] = best; si[wid] = bidx; }
    __syncthreads();

    if (wid == 0) {
        best = (lane < NWARPS) ? sv[lane] : -INFINITY;
        bidx = (lane < NWARPS) ? si[lane] : 0x7fffffff;
        #pragma unroll
        for (int off = NWARPS / 2; off > 0; off >>= 1) {
            const float ov = __shfl_down_sync(0xffffffffu, best, off);
            const int   oi = __shfl_down_sync(0xffffffffu, bidx, off);
            if (ov > best || (ov == best && oi < bidx)) { best = ov; bidx = oi; }
        }
        if (lane == 0) {
            const float* q = reinterpret_cast<const float*>(rrow) + (long long)bidx * 5;
            float* o = out + (size_t)row * 4;
            o[0] = q[1];
            o[1] = q[2];
            o[2] = q[3];
            o[3] = q[4];
            out[(size_t)N_ROWS * 4 + row] =
                reinterpret_cast<const float*>(srow)[bidx * 2 + 1];
        }
    }
}

extern "C" void kernel_launch(void* const* d_in, const int* in_sizes, int n_in,
                              void* d_out, int out_size)
{
    const float* rois   = (const float*)d_in[0];
    const float* rpn    = (const float*)d_in[1];
    const float* scores = (const float*)d_in[2];
    float* out = (float*)d_out;

    trnms_kernel<<<N_ROWS, THREADS>>>(rois, rpn, scores, out);
}

// round 14
// speedup vs baseline: 1.0376x; 1.0318x over previous
#include <cuda_runtime.h>
#include <math.h>
#include <stdint.h>

#define N_ROWS   8192
#define N_PROP   2000
#define THREADS  256
#define NWARPS   (THREADS / 32)
#define CHUNK    256
#define NCHUNKS  8                 // 7*256 + 208 = 2000
#define TAILN    208
#define NBUF     3
#define RPN_CB   (CHUNK * 5 * 4)   // 5120 B (16B mult)
#define SC_CB    (CHUNK * 2 * 4)   // 2048 B
#define RPN_TB   (TAILN * 5 * 4)   // 4160 B (16B mult)
#define SC_TB    (TAILN * 2 * 4)   // 1664 B (16B mult)
#define BUF_STRIDE (RPN_CB + SC_CB)   // 7168, 128B-aligned

// d_in[0]=rois (N,4), d_in[1]=rpn_rois (N,NP,5), d_in[2]=scores (N,NP,2)
// d_out = [sel_rpn_rois (N,4) | sel_scores (N,1)]

struct RefStats { float x, y, s, inv_s, r_max, piw, wsq; };

__device__ __forceinline__ uint32_t smem_u32(const void* p) {
    uint32_t a;
    asm("{ .reg .u64 t; cvta.to.shared.u64 t, %1; cvt.u32.u64 %0, t; }"
        : "=r"(a) : "l"(p));
    return a;
}
__device__ __forceinline__ float rcp_approx(float a) {
    float r; asm("rcp.approx.ftz.f32 %0, %1;" : "=f"(r) : "f"(a)); return r;
}
__device__ __forceinline__ float ex2_approx(float a) {
    float r; asm("ex2.approx.ftz.f32 %0, %1;" : "=f"(r) : "f"(a)); return r;
}
__device__ __forceinline__ void mbar_init(uint32_t mbar, uint32_t cnt) {
    asm volatile("mbarrier.init.shared.b64 [%0], %1;" :: "r"(mbar), "r"(cnt) : "memory");
}
__device__ __forceinline__ void mbar_arrive(uint32_t mbar) {
    asm volatile("mbarrier.arrive.shared.b64 _, [%0];" :: "r"(mbar) : "memory");
}
__device__ __forceinline__ void mbar_expect_tx(uint32_t mbar, uint32_t bytes) {
    asm volatile("mbarrier.arrive.expect_tx.shared.b64 _, [%0], %1;"
                 :: "r"(mbar), "r"(bytes) : "memory");
}
__device__ __forceinline__ void bulk_g2s(uint32_t dst, const void* src,
                                         uint32_t bytes, uint32_t mbar) {
    asm volatile("cp.async.bulk.shared::cta.global.mbarrier::complete_tx::bytes "
                 "[%0], [%1], %2, [%3];"
                 :: "r"(dst), "l"(src), "r"(bytes), "r"(mbar) : "memory");
}
__device__ __forceinline__ void mbar_wait(uint32_t mbar, uint32_t parity) {
    asm volatile(
        "{\n\t"
        ".reg .pred P;\n\t"
        "WL_%=:\n\t"
        "mbarrier.try_wait.parity.acquire.cta.shared::cta.b64 P, [%0], %1, 0x989680;\n\t"
        "@P bra.uni WD_%=;\n\t"
        "bra.uni WL_%=;\n\t"
        "WD_%=:\n\t"
        "}" :: "r"(mbar), "r"(parity) : "memory");
}
__device__ __forceinline__ void mbar_wait_relaxed(uint32_t mbar, uint32_t parity) {
    asm volatile(
        "{\n\t"
        ".reg .pred P;\n\t"
        "WL_%=:\n\t"
        "mbarrier.try_wait.parity.relaxed.cta.shared::cta.b64 P, [%0], %1, 0x989680;\n\t"
        "@P bra.uni WD_%=;\n\t"
        "bra.uni WL_%=;\n\t"
        "WD_%=:\n\t"
        "}" :: "r"(mbar), "r"(parity) : "memory");
}

// exp(y) for y <= 0, ~2ulp
__device__ __forceinline__ float fast_exp_neg(float y) {
    float z  = fmaxf(y * 1.4426950408889634f, -127.0f);
    float fn = rintf(z);
    float m  = ex2_approx(z - fn);
    float sc = __int_as_float(((int)fn + 127) << 23);
    return m * sc;
}

// hanning(t) = cos^2(t/2), Taylor on t/2 in [0, 1.6], err < 1e-8
__device__ __forceinline__ float hann_from_t(float t) {
    float th = t * 0.5f;
    float u  = th * th;
    float P = 2.0876757e-9f;
    P = fmaf(P, u, -2.7557319e-7f);
    P = fmaf(P, u,  2.4801587e-5f);
    P = fmaf(P, u, -1.3888889e-3f);
    P = fmaf(P, u,  4.1666667e-2f);
    P = fmaf(P, u, -0.5f);
    P = fmaf(P, u,  1.0f);
    return P * P;
}

__device__ __forceinline__ float prop_score(const RefStats& R,
                                            float a0, float a1, float a2, float a3,
                                            float sc)
{
    const float x_ = (a0 + a2) * 0.5f;
    const float y_ = (a1 + a3) * 0.5f;
    const float w_ = fabsf(a0 - a2) + 1e-4f;
    const float h_ = fabsf(a1 - a3) + 1e-4f;
    const float p_ = (w_ + h_) * 0.5f;
    const float q  = (w_ + p_) * (h_ + p_);
    const float s_ = q * rsqrtf(q);

    const float smax = fmaxf(R.s * rcp_approx(s_), s_ * R.inv_s);
    const float pen  = fast_exp_neg(fmaf(smax * R.r_max, -0.055f, 0.055f));

    const float dx  = R.x - x_;
    const float dy  = R.y - y_;
    const float d2  = fmaf(dx, dx, dy * dy);
    const float d2g = fmaxf(d2, 1e-36f);
    const float dist = d2g * rsqrtf(d2g);
    const float t   = fminf(dist * R.piw, 3.2f);
    float han = hann_from_t(t);
    han = (d2 > R.wsq) ? 0.0f : han;

    return fmaf(sc, pen, 0.42f * han);
}

__device__ __forceinline__ void issue_chunk(int c, uint32_t mbf, uint32_t bb,
                                            const char* rrow, const char* srow)
{
    const int b = c % NBUF;
    const uint32_t m = mbf + 8u * b;
    const uint32_t d = bb + b * BUF_STRIDE;
    const uint32_t rbytes = (c == NCHUNKS - 1) ? RPN_TB : RPN_CB;
    const uint32_t sbytes = (c == NCHUNKS - 1) ? SC_TB  : SC_CB;
    mbar_expect_tx(m, rbytes + sbytes);
    bulk_g2s(d,          rrow + (size_t)c * RPN_CB, rbytes, m);
    bulk_g2s(d + RPN_CB, srow + (size_t)c * SC_CB,  sbytes, m);
}

__global__ __launch_bounds__(THREADS)
void trnms_kernel(const float* __restrict__ rois,
                  const float* __restrict__ rpn,
                  const float* __restrict__ scores,
                  float* __restrict__ out)
{
    const int row = blockIdx.x;
    const int tid = threadIdx.x;
    const int lane = tid & 31;
    const int wid  = tid >> 5;

    __shared__ __align__(128) unsigned char sbuf[NBUF * BUF_STRIDE];  // 21504 B
    __shared__ __align__(8)  uint64_t mbar_full[NBUF];
    __shared__ __align__(8)  uint64_t mbar_empty[NBUF];
    __shared__ float sv[NWARPS];
    __shared__ int   si[NWARPS];

    const uint32_t mbf = smem_u32(mbar_full);
    const uint32_t mbe = smem_u32(mbar_empty);
    const uint32_t bb  = smem_u32(sbuf);

    const char* rrow = (const char*)rpn    + (size_t)row * (N_PROP * 5 * 4);
    const char* srow = (const char*)scores + (size_t)row * (N_PROP * 2 * 4);

    // Copies first — nothing depends on rois yet.
    if (tid == 0) {
        #pragma unroll
        for (int b = 0; b < NBUF; b++) {
            mbar_init(mbf + 8u * b, 1);
            mbar_init(mbe + 8u * b, NWARPS);
        }
        asm volatile("fence.proxy.async.shared::cta;" ::: "memory");
    }
    __syncthreads();
    if (tid == 0) {
        #pragma unroll
        for (int c = 0; c < NBUF; c++) issue_chunk(c, mbf, bb, rrow, srow);
    }

    RefStats R;
    {
        const float4 rr = *reinterpret_cast<const float4*>(rois + (size_t)row * 4);
        R.x = (rr.x + rr.z) * 0.5f;
        R.y = (rr.y + rr.w) * 0.5f;
        const float w = fabsf(rr.x - rr.z) + 1e-4f;
        const float h = fabsf(rr.y - rr.w) + 1e-4f;
        const float p = (w + h) * 0.5f;
        R.s = sqrtf((w + p) * (h + p));
        R.inv_s = __fdiv_rn(1.0f, R.s);
        const float ratio = __fdiv_rn(w, h);
        R.r_max = fmaxf(ratio, __fdiv_rn(1.0f, ratio));
        const float window = R.s * 2.0f;
        R.piw = __fdiv_rn(3.14159274101257324219f, window);
        R.wsq = window * window;
    }

    // Hoisted per-thread smem byte offsets (constant across chunks; +4B skips field 0)
    const uint32_t roff = (uint32_t)tid * 20u + 4u;   // rpn: tid*5 floats, fields 1..4
    const uint32_t soff = (uint32_t)tid * 8u;         // scores: tid*2 floats

    float best = -INFINITY;
    int   bidx = 0x7fffffff;

    #pragma unroll
    for (int c = 0; c < NCHUNKS; c++) {
        const int b   = c % NBUF;
        const int phf = (c / NBUF) & 1;
        mbar_wait(mbf + 8u * b, phf);          // consumer: data ready

        const int cnt = (c == NCHUNKS - 1) ? TAILN : CHUNK;   // 256 for c<7
        const bool active = (tid < cnt);

        // ---- loads only: pull the 5 values into registers ----
        float a0 = 0.f, a1 = 0.f, a2 = 0.f, a3 = 0.f, scv = 0.f;
        if (active) {
            const char* base = (const char*)sbuf + b * BUF_STRIDE;
            a0 = *reinterpret_cast<const float*>(base + roff);
            a1 = *reinterpret_cast<const float*>(base + roff + 4);
            a2 = *reinterpret_cast<const float*>(base + roff + 8);
            a3 = *reinterpret_cast<const float*>(base + roff + 12);
            const float2 s2 = *reinterpret_cast<const float2*>(base + RPN_CB + soff);
            scv = s2.y;
        }

        // ---- EARLY buffer release: data is in registers; recycle while we compute ----
        if (c + NBUF < NCHUNKS) {
            __syncwarp();
            if (lane == 0) mbar_arrive(mbe + 8u * b);   // release orders prior LDS
            if (tid == 0) {
                mbar_wait_relaxed(mbe + 8u * b, (c / NBUF) & 1);
                issue_chunk(c + NBUF, mbf, bb, rrow, srow);
            }
        }

        // ---- math overlapped with the in-flight refill ----
        if (active) {
            const float pw = prop_score(R, a0, a1, a2, a3, scv);
            const int j = c * CHUNK + tid;     // ascending per thread
            if (pw > best) { best = pw; bidx = j; }
        }
    }

    // ---- block argmax reduction, first-index wins on ties ----
    #pragma unroll
    for (int off = 16; off > 0; off >>= 1) {
        const float ov = __shfl_down_sync(0xffffffffu, best, off);
        const int   oi = __shfl_down_sync(0xffffffffu, bidx, off);
        if (ov > best || (ov == best && oi < bidx)) { best = ov; bidx = oi; }
    }
    if (lane == 0) { sv[wid] = best; si[wid] = bidx; }
    __syncthreads();

    if (wid == 0) {
        best = (lane < NWARPS) ? sv[lane] : -INFINITY;
        bidx = (lane < NWARPS) ? si[lane] : 0x7fffffff;
        #pragma unroll
        for (int off = NWARPS / 2; off > 0; off >>= 1) {
            const float ov = __shfl_down_sync(0xffffffffu, best, off);
            const int   oi = __shfl_down_sync(0xffffffffu, bidx, off);
            if (ov > best || (ov == best && oi < bidx)) { best = ov; bidx = oi; }
        }
        if (lane == 0) {
            const float* q = reinterpret_cast<const float*>(rrow) + (long long)bidx * 5;
            float* o = out + (size_t)row * 4;
            o[0] = q[1];
            o[1] = q[2];
            o[2] = q[3];
            o[3] = q[4];
            out[(size_t)N_ROWS * 4 + row] =
                reinterpret_cast<const float*>(srow)[bidx * 2 + 1];
        }
    }
}

extern "C" void kernel_launch(void* const* d_in, const int* in_sizes, int n_in,
                              void* d_out, int out_size)
{
    const float* rois   = (const float*)d_in[0];
    const float* rpn    = (const float*)d_in[1];
    const float* scores = (const float*)d_in[2];
    float* out = (float*)d_out;

    trnms_kernel<<<N_ROWS, THREADS>>>(rois, rpn, scores, out);
}